// round 3
// baseline (speedup 1.0000x reference)
#include <cuda_runtime.h>
#include <cuda_bf16.h>
#include <cstdint>

// Problem constants (fixed shapes per reference)
#define IN_F    4096
#define OUT_F   16384
#define ACT_IN  2048
#define ACT_OUT 8192
#define NROWS   8192   // B*S = 4*2048

// GEMM tiling
#define BM 128
#define BN 128
#define BK 16
#define TM 8
#define TN 8
#define NTHREADS 256

// Pre-gathered activation scratch: x_active[m][k] = x[m*IN_F + in_idx[k]]
// 8192 * 2048 * 4B = 64 MB static device array (allocation-free rule).
__device__ float g_xa[(size_t)NROWS * ACT_IN];

// ---------------------------------------------------------------------------
// Kernel 1: gather active input columns into dense [NROWS, ACT_IN] scratch.
// Coalesced-ish reads (sorted indices, ~50% density -> ~2x sector amp),
// fully coalesced writes.
// ---------------------------------------------------------------------------
__global__ void nsl_gather(const float* __restrict__ x,
                           const int* __restrict__ in_idx) {
    const int k = blockIdx.x * blockDim.x + threadIdx.x;   // 0..ACT_IN-1
    const int m = blockIdx.y;                              // 0..NROWS-1
    if (k < ACT_IN) {
        const int c = __ldg(&in_idx[k]);
        g_xa[(size_t)m * ACT_IN + k] = __ldg(&x[(size_t)m * IN_F + c]);
    }
}

// ---------------------------------------------------------------------------
// Kernel 2: C[m, out_idx[n]] = sum_k xa[m,k] * W[n,k] + bias[n]
// Classic 128x128x16 fp32 SGEMM, 256 threads, 8x8 microtile per thread,
// register-prefetch double buffering. Scatter + bias fused in epilogue.
// ---------------------------------------------------------------------------
__global__ __launch_bounds__(NTHREADS, 2)
void nsl_gemm(const float* __restrict__ W,
              const float* __restrict__ bias,
              const int*   __restrict__ out_idx,
              float*       __restrict__ out) {
    __shared__ float As[BK][BM];   // [k][m]
    __shared__ float Bs[BK][BN];   // [k][n]

    const int m0 = blockIdx.y * BM;
    const int n0 = blockIdx.x * BN;
    const int tid = threadIdx.x;

    // Global-load mapping: tile is 128 rows x 16 k (= 128 x 4 float4).
    // Linear id over 512 float4 slots; each thread handles id = tid, tid+256.
    const int r0  = tid >> 2;          // row slot 0..63 (first half)
    const int kv0 = tid & 3;           // float4 index in k (0..3)
    // second slot: id2 = tid + 256 -> row += 64
    const int r1  = r0 + 64;
    const int kv1 = kv0;

    // Compute mapping: 16x16 thread grid of 8x8 microtiles
    const int tx = tid & 15;           // 0..15 -> n direction
    const int ty = tid >> 4;           // 0..15 -> m direction
    const int tm = ty * TM;
    const int tn = tx * TN;

    const float* A = g_xa + (size_t)m0 * ACT_IN;
    const float* B = W    + (size_t)n0 * ACT_IN;

    float acc[TM][TN];
    #pragma unroll
    for (int i = 0; i < TM; i++)
        #pragma unroll
        for (int j = 0; j < TN; j++)
            acc[i][j] = 0.0f;

    // ---- prologue: load k-tile 0 straight into smem ----
    {
        float4 a0 = *(const float4*)&A[(size_t)r0 * ACT_IN + kv0 * 4];
        float4 a1 = *(const float4*)&A[(size_t)r1 * ACT_IN + kv1 * 4];
        float4 b0 = *(const float4*)&B[(size_t)r0 * ACT_IN + kv0 * 4];
        float4 b1 = *(const float4*)&B[(size_t)r1 * ACT_IN + kv1 * 4];
        As[kv0*4+0][r0] = a0.x; As[kv0*4+1][r0] = a0.y;
        As[kv0*4+2][r0] = a0.z; As[kv0*4+3][r0] = a0.w;
        As[kv1*4+0][r1] = a1.x; As[kv1*4+1][r1] = a1.y;
        As[kv1*4+2][r1] = a1.z; As[kv1*4+3][r1] = a1.w;
        Bs[kv0*4+0][r0] = b0.x; Bs[kv0*4+1][r0] = b0.y;
        Bs[kv0*4+2][r0] = b0.z; Bs[kv0*4+3][r0] = b0.w;
        Bs[kv1*4+0][r1] = b1.x; Bs[kv1*4+1][r1] = b1.y;
        Bs[kv1*4+2][r1] = b1.z; Bs[kv1*4+3][r1] = b1.w;
    }
    __syncthreads();

    const int NT = ACT_IN / BK;   // 128 k-tiles
    float4 pa0, pa1, pb0, pb1;

    for (int kt = 0; kt < NT; kt++) {
        // prefetch next k-tile to registers
        if (kt + 1 < NT) {
            const int ko = (kt + 1) * BK;
            pa0 = *(const float4*)&A[(size_t)r0 * ACT_IN + ko + kv0 * 4];
            pa1 = *(const float4*)&A[(size_t)r1 * ACT_IN + ko + kv1 * 4];
            pb0 = *(const float4*)&B[(size_t)r0 * ACT_IN + ko + kv0 * 4];
            pb1 = *(const float4*)&B[(size_t)r1 * ACT_IN + ko + kv1 * 4];
        }

        // compute on current smem tile
        #pragma unroll
        for (int kk = 0; kk < BK; kk++) {
            float a_frag[TM], b_frag[TN];
            float4 av0 = *(const float4*)&As[kk][tm];
            float4 av1 = *(const float4*)&As[kk][tm + 4];
            float4 bv0 = *(const float4*)&Bs[kk][tn];
            float4 bv1 = *(const float4*)&Bs[kk][tn + 4];
            a_frag[0]=av0.x; a_frag[1]=av0.y; a_frag[2]=av0.z; a_frag[3]=av0.w;
            a_frag[4]=av1.x; a_frag[5]=av1.y; a_frag[6]=av1.z; a_frag[7]=av1.w;
            b_frag[0]=bv0.x; b_frag[1]=bv0.y; b_frag[2]=bv0.z; b_frag[3]=bv0.w;
            b_frag[4]=bv1.x; b_frag[5]=bv1.y; b_frag[6]=bv1.z; b_frag[7]=bv1.w;
            #pragma unroll
            for (int i = 0; i < TM; i++)
                #pragma unroll
                for (int j = 0; j < TN; j++)
                    acc[i][j] = fmaf(a_frag[i], b_frag[j], acc[i][j]);
        }
        __syncthreads();

        // commit prefetched tile to smem
        if (kt + 1 < NT) {
            As[kv0*4+0][r0] = pa0.x; As[kv0*4+1][r0] = pa0.y;
            As[kv0*4+2][r0] = pa0.z; As[kv0*4+3][r0] = pa0.w;
            As[kv1*4+0][r1] = pa1.x; As[kv1*4+1][r1] = pa1.y;
            As[kv1*4+2][r1] = pa1.z; As[kv1*4+3][r1] = pa1.w;
            Bs[kv0*4+0][r0] = pb0.x; Bs[kv0*4+1][r0] = pb0.y;
            Bs[kv0*4+2][r0] = pb0.z; Bs[kv0*4+3][r0] = pb0.w;
            Bs[kv1*4+0][r1] = pb1.x; Bs[kv1*4+1][r1] = pb1.y;
            Bs[kv1*4+2][r1] = pb1.z; Bs[kv1*4+3][r1] = pb1.w;
            __syncthreads();
        }
    }

    // ---- epilogue: bias + scatter to sparse output columns ----
    int   oc[TN];
    float bv[TN];
    #pragma unroll
    for (int j = 0; j < TN; j++) {
        oc[j] = __ldg(&out_idx[n0 + tn + j]);
        bv[j] = __ldg(&bias[n0 + tn + j]);
    }
    #pragma unroll
    for (int i = 0; i < TM; i++) {
        float* orow = out + (size_t)(m0 + tm + i) * OUT_F;
        #pragma unroll
        for (int j = 0; j < TN; j++)
            orow[oc[j]] = acc[i][j] + bv[j];
    }
}

// ---------------------------------------------------------------------------
// Launch
// ---------------------------------------------------------------------------
extern "C" void kernel_launch(void* const* d_in, const int* in_sizes, int n_in,
                              void* d_out, int out_size) {
    const float* x       = (const float*)d_in[0];
    const float* weight  = (const float*)d_in[1];
    const float* bias    = (const float*)d_in[2];
    const int*   in_idx  = (const int*)d_in[3];
    const int*   out_idx = (const int*)d_in[4];
    float* out = (float*)d_out;

    // 1) zero the full output (inactive columns must be 0; poisoned 0xAA)
    cudaMemsetAsync(out, 0, (size_t)out_size * sizeof(float), 0);

    // 2) gather active input columns -> dense scratch
    {
        dim3 grid(ACT_IN / 256, NROWS);
        nsl_gather<<<grid, 256>>>(x, in_idx);
    }

    // 3) GEMM + bias + scatter
    {
        dim3 grid(ACT_OUT / BN, NROWS / BM);   // 64 x 64
        nsl_gemm<<<grid, NTHREADS>>>(weight, bias, out_idx, out);
    }
}

// round 5
// speedup vs baseline: 2.4521x; 2.4521x over previous
#include <cuda_runtime.h>
#include <cuda_bf16.h>
#include <cstdint>

// ---------------------------------------------------------------------------
// Problem constants
// ---------------------------------------------------------------------------
#define IN_F    4096
#define OUT_F   16384
#define ACT_IN  2048
#define ACT_OUT 8192
#define NROWS   8192      // B*S

// GEMM tiling
#define BM 128
#define BN 128
#define KC 64                    // K elements per stage (128 B/row in smem)
#define NSTAGE (ACT_IN / KC)     // 32
#define NTH 256                  // 8 warps: 2 (M) x 4 (N), warp tile 64x32

// SMEM: 2 stages x { Ah 16K | Al 16K | Bh 16K | Bl 16K } = 128 KB
#define T_AH 0
#define T_AL 16384
#define T_BH 32768
#define T_BL 49152
#define STAGE_BYTES 65536
#define SMEM_TOTAL  131072

// bf16-split operand scratch (allocation-free rule: __device__ globals)
__device__ __nv_bfloat16 g_Ah[(size_t)NROWS * ACT_IN];
__device__ __nv_bfloat16 g_Al[(size_t)NROWS * ACT_IN];
__device__ __nv_bfloat16 g_Bh[(size_t)ACT_OUT * ACT_IN];
__device__ __nv_bfloat16 g_Bl[(size_t)ACT_OUT * ACT_IN];

// ---------------------------------------------------------------------------
// PTX helpers (sm_80-baseline instructions only — no arch-feature ops,
// since the harness lowers through plain compute_103 PTX)
// ---------------------------------------------------------------------------
__device__ __forceinline__ uint32_t smem_u32(const void* p) {
    uint32_t a;
    asm("{ .reg .u64 t; cvta.to.shared.u64 t, %1; cvt.u32.u64 %0, t; }"
        : "=r"(a) : "l"(p));
    return a;
}

#define SWZ(o) ((o) ^ (((o) >> 3) & 0x70))   // SW128: 16B-granular xor swizzle

#define CPA16(sa, gp) \
    asm volatile("cp.async.cg.shared.global [%0], [%1], 16;" :: "r"(sa), "l"(gp) : "memory")
#define CPA_COMMIT() asm volatile("cp.async.commit_group;" ::: "memory")
#define CPA_WAIT(n)  asm volatile("cp.async.wait_group %0;" :: "n"(n) : "memory")

#define LDSM4(r0, r1, r2, r3, a) \
    asm volatile("ldmatrix.sync.aligned.m8n8.x4.shared.b16 {%0,%1,%2,%3}, [%4];" \
                 : "=r"(r0), "=r"(r1), "=r"(r2), "=r"(r3) : "r"(a))

// D = A*B + D, bf16 inputs, fp32 accum.  A frag 4xb32, B frag 2xb32, C 4xf32.
#define MMA(c, a0, a1, a2, a3, b0, b1) \
    asm volatile("mma.sync.aligned.m16n8k16.row.col.f32.bf16.bf16.f32 " \
                 "{%0,%1,%2,%3}, {%4,%5,%6,%7}, {%8,%9}, {%0,%1,%2,%3};" \
                 : "+f"((c)[0]), "+f"((c)[1]), "+f"((c)[2]), "+f"((c)[3]) \
                 : "r"(a0), "r"(a1), "r"(a2), "r"(a3), "r"(b0), "r"(b1))

// ---------------------------------------------------------------------------
// Pre-pass 1: gather active input cols + split fp32 -> bf16 hi/lo
// ---------------------------------------------------------------------------
__global__ void nsl_split_x(const float* __restrict__ x,
                            const int* __restrict__ in_idx) {
    const int k = blockIdx.x * blockDim.x + threadIdx.x;
    const int m = blockIdx.y;
    const int c = __ldg(&in_idx[k]);
    const float v = __ldg(&x[(size_t)m * IN_F + c]);
    const __nv_bfloat16 h = __float2bfloat16(v);
    const __nv_bfloat16 l = __float2bfloat16(v - __bfloat162float(h));
    g_Ah[(size_t)m * ACT_IN + k] = h;
    g_Al[(size_t)m * ACT_IN + k] = l;
}

// Pre-pass 2: split weight fp32 -> bf16 hi/lo
__global__ void nsl_split_w(const float* __restrict__ w) {
    const size_t i = blockIdx.x * (size_t)blockDim.x + threadIdx.x;
    const float v = __ldg(&w[i]);
    const __nv_bfloat16 h = __float2bfloat16(v);
    const __nv_bfloat16 l = __float2bfloat16(v - __bfloat162float(h));
    g_Bh[i] = h;
    g_Bl[i] = l;
}

// ---------------------------------------------------------------------------
// Main GEMM: C[m, out_idx[n]] = sum_k (Ah+Al)[m,k] * (Bh+Bl)[n,k] + bias[n]
// via 3 HMMA products with fp32 register accumulation.
// ---------------------------------------------------------------------------
__global__ __launch_bounds__(NTH, 1)
void nsl_mma(const float* __restrict__ bias,
             const int*   __restrict__ out_idx,
             float*       __restrict__ out) {
    extern __shared__ __align__(1024) char smem[];
    const uint32_t sb = smem_u32(smem);
    const int tid  = threadIdx.x;
    const int wid  = tid >> 5;
    const int lane = tid & 31;
    const int m0 = blockIdx.y * BM;
    const int n0 = blockIdx.x * BN;

    const int warp_m = wid >> 2;       // 0..1  -> 64-row slab
    const int warp_n = wid & 3;        // 0..3  -> 32-col slab

    // ---- cp.async slot mapping: per tile 128 rows x 8 x 16B = 1024 chunks,
    // 4 per thread; same (row,chunk) used for all four tiles.
    int      gOff[4];
    uint32_t sOff[4];
#pragma unroll
    for (int i = 0; i < 4; i++) {
        const int id = tid + i * NTH;
        const int r = id >> 3, cv = id & 7;
        gOff[i] = r * ACT_IN + cv * 8;                  // elements
        sOff[i] = SWZ((uint32_t)(r * 128 + cv * 16));   // swizzled bytes
    }
    const __nv_bfloat16* pAh = g_Ah + (size_t)m0 * ACT_IN;
    const __nv_bfloat16* pAl = g_Al + (size_t)m0 * ACT_IN;
    const __nv_bfloat16* pBh = g_Bh + (size_t)n0 * ACT_IN;
    const __nv_bfloat16* pBl = g_Bl + (size_t)n0 * ACT_IN;

    auto load_stage = [&](int s, int b) {
        const uint32_t base = sb + b * STAGE_BYTES;
        const int ke = s * KC;
#pragma unroll
        for (int i = 0; i < 4; i++) {
            CPA16(base + T_AH + sOff[i], pAh + ke + gOff[i]);
            CPA16(base + T_AL + sOff[i], pAl + ke + gOff[i]);
            CPA16(base + T_BH + sOff[i], pBh + ke + gOff[i]);
            CPA16(base + T_BL + sOff[i], pBl + ke + gOff[i]);
        }
        CPA_COMMIT();
    };

    // ---- ldmatrix lane addressing (within a tile, before stage/tile base) ----
    // A (x4, m16 x k16): rows m .. m+15 (lane&15), k halves by lane>>4.
    const int lrow  = lane & 15;
    const int lkoff = (lane >> 4) * 16;   // bytes

    // ---- accumulators: warp tile 64x32 = 4 m-tiles x 4 n-tiles x 4 f32 ----
    float acc[4][4][4];
#pragma unroll
    for (int i = 0; i < 4; i++)
#pragma unroll
        for (int j = 0; j < 4; j++)
#pragma unroll
            for (int q = 0; q < 4; q++) acc[i][j][q] = 0.0f;

    // ---- pipeline prologue ----
    load_stage(0, 0);
    load_stage(1, 1);

    for (int s = 0; s < NSTAGE; s++) {
        if (s < NSTAGE - 1) { CPA_WAIT(1); } else { CPA_WAIT(0); }
        __syncthreads();

        const uint32_t base = sb + (s & 1) * STAGE_BYTES;
        const uint32_t aRow = (uint32_t)((warp_m * 64 + lrow) * 128);
        const uint32_t bRow = (uint32_t)((warp_n * 32 + lrow) * 128);

#pragma unroll
        for (int ks = 0; ks < 4; ks++) {
            const uint32_t kb = (uint32_t)(ks * 32 + lkoff);

            // B-hi fragments: 2 x ldmatrix.x4 cover n32 x k16
            uint32_t bh[8];
            LDSM4(bh[0], bh[1], bh[2], bh[3], base + T_BH + SWZ(bRow + kb));
            LDSM4(bh[4], bh[5], bh[6], bh[7], base + T_BH + SWZ(bRow + 16 * 128 + kb));
            // A-hi fragments: 4 m-tiles
            uint32_t ah[4][4];
#pragma unroll
            for (int mt = 0; mt < 4; mt++)
                LDSM4(ah[mt][0], ah[mt][1], ah[mt][2], ah[mt][3],
                      base + T_AH + SWZ(aRow + (uint32_t)(mt * 16 * 128) + kb));

            // P1: Ah * Bh
#pragma unroll
            for (int mt = 0; mt < 4; mt++) {
                MMA(acc[mt][0], ah[mt][0], ah[mt][1], ah[mt][2], ah[mt][3], bh[0], bh[2]);
                MMA(acc[mt][1], ah[mt][0], ah[mt][1], ah[mt][2], ah[mt][3], bh[1], bh[3]);
                MMA(acc[mt][2], ah[mt][0], ah[mt][1], ah[mt][2], ah[mt][3], bh[4], bh[6]);
                MMA(acc[mt][3], ah[mt][0], ah[mt][1], ah[mt][2], ah[mt][3], bh[5], bh[7]);
            }

            // P2: Ah * Bl  (bl reuses regs after P2 ends)
            {
                uint32_t bl[8];
                LDSM4(bl[0], bl[1], bl[2], bl[3], base + T_BL + SWZ(bRow + kb));
                LDSM4(bl[4], bl[5], bl[6], bl[7], base + T_BL + SWZ(bRow + 16 * 128 + kb));
#pragma unroll
                for (int mt = 0; mt < 4; mt++) {
                    MMA(acc[mt][0], ah[mt][0], ah[mt][1], ah[mt][2], ah[mt][3], bl[0], bl[2]);
                    MMA(acc[mt][1], ah[mt][0], ah[mt][1], ah[mt][2], ah[mt][3], bl[1], bl[3]);
                    MMA(acc[mt][2], ah[mt][0], ah[mt][1], ah[mt][2], ah[mt][3], bl[4], bl[6]);
                    MMA(acc[mt][3], ah[mt][0], ah[mt][1], ah[mt][2], ah[mt][3], bl[5], bl[7]);
                }
            }

            // P3: Al * Bh  (al reuses ah's register space per m-tile)
#pragma unroll
            for (int mt = 0; mt < 4; mt++) {
                uint32_t al[4];
                LDSM4(al[0], al[1], al[2], al[3],
                      base + T_AL + SWZ(aRow + (uint32_t)(mt * 16 * 128) + kb));
                MMA(acc[mt][0], al[0], al[1], al[2], al[3], bh[0], bh[2]);
                MMA(acc[mt][1], al[0], al[1], al[2], al[3], bh[1], bh[3]);
                MMA(acc[mt][2], al[0], al[1], al[2], al[3], bh[4], bh[6]);
                MMA(acc[mt][3], al[0], al[1], al[2], al[3], bh[5], bh[7]);
            }
        }

        __syncthreads();                       // all warps done with buf (s&1)
        if (s + 2 < NSTAGE) load_stage(s + 2, s & 1);
    }

    // ---- epilogue: bias + scatter straight from C fragments ----
    // C frag: c0,c1 -> (row t/4, col 2*(t%4)+{0,1}); c2,c3 -> row+8.
    const int trow = lane >> 2;
    const int tcol = (lane & 3) * 2;
    int   oc0[4], oc1[4];
    float bv0[4], bv1[4];
#pragma unroll
    for (int nt = 0; nt < 4; nt++) {
        const int n = n0 + warp_n * 32 + nt * 8 + tcol;
        oc0[nt] = __ldg(&out_idx[n]);     oc1[nt] = __ldg(&out_idx[n + 1]);
        bv0[nt] = __ldg(&bias[n]);        bv1[nt] = __ldg(&bias[n + 1]);
    }
#pragma unroll
    for (int mt = 0; mt < 4; mt++) {
        const int m = m0 + warp_m * 64 + mt * 16 + trow;
        float* r0 = out + (size_t)m * OUT_F;
        float* r1 = out + (size_t)(m + 8) * OUT_F;
#pragma unroll
        for (int nt = 0; nt < 4; nt++) {
            r0[oc0[nt]] = acc[mt][nt][0] + bv0[nt];
            r0[oc1[nt]] = acc[mt][nt][1] + bv1[nt];
            r1[oc0[nt]] = acc[mt][nt][2] + bv0[nt];
            r1[oc1[nt]] = acc[mt][nt][3] + bv1[nt];
        }
    }
}

// ---------------------------------------------------------------------------
// Launch
// ---------------------------------------------------------------------------
extern "C" void kernel_launch(void* const* d_in, const int* in_sizes, int n_in,
                              void* d_out, int out_size) {
    const float* x       = (const float*)d_in[0];
    const float* weight  = (const float*)d_in[1];
    const float* bias    = (const float*)d_in[2];
    const int*   in_idx  = (const int*)d_in[3];
    const int*   out_idx = (const int*)d_in[4];
    float* out = (float*)d_out;

    // zero full output (inactive columns must be 0; buffer is poisoned)
    cudaMemsetAsync(out, 0, (size_t)out_size * sizeof(float), 0);

    // pre-pass: gather + bf16 split
    {
        dim3 g(ACT_IN / 256, NROWS);
        nsl_split_x<<<g, 256>>>(x, in_idx);
    }
    nsl_split_w<<<(ACT_OUT * ACT_IN) / 256, 256>>>(weight);

    // tensor-core GEMM (mma.sync) + bias + scatter
    cudaFuncSetAttribute(nsl_mma, cudaFuncAttributeMaxDynamicSharedMemorySize,
                         SMEM_TOTAL);
    dim3 grid(ACT_OUT / BN, NROWS / BM);   // 64 x 64
    nsl_mma<<<grid, NTH, SMEM_TOTAL>>>(bias, out_idx, out);
}

// round 6
// speedup vs baseline: 2.4541x; 1.0008x over previous
#include <cuda_runtime.h>
#include <cuda_bf16.h>
#include <cstdint>

// ---------------------------------------------------------------------------
// Problem constants
// ---------------------------------------------------------------------------
#define IN_F    4096
#define OUT_F   16384
#define ACT_IN  2048
#define ACT_OUT 8192
#define NROWS   8192      // B*S

// GEMM tiling
#define BM 128
#define BN 128
#define KC 64                    // K elements per stage (128 B/row in smem)
#define NSTAGE (ACT_IN / KC)     // 32
#define NTH 256                  // 8 warps: 2 (M) x 4 (N), warp tile 64x32

// SMEM: 2 stages x { Ah 16K | Al 16K | Bh 16K | Bl 16K } = 128 KB
#define T_AH 0
#define T_AL 16384
#define T_BH 32768
#define T_BL 49152
#define STAGE_BYTES 65536
#define SMEM_TOTAL  131072

// bf16-split operand scratch (allocation-free rule: __device__ globals)
__device__ __nv_bfloat16 g_Ah[(size_t)NROWS * ACT_IN];
__device__ __nv_bfloat16 g_Al[(size_t)NROWS * ACT_IN];
__device__ __nv_bfloat16 g_Bh[(size_t)ACT_OUT * ACT_IN];
__device__ __nv_bfloat16 g_Bl[(size_t)ACT_OUT * ACT_IN];

// ---------------------------------------------------------------------------
// PTX helpers (sm_80-baseline instructions only — no arch-feature ops,
// since the harness lowers through plain compute_103 PTX)
// ---------------------------------------------------------------------------
__device__ __forceinline__ uint32_t smem_u32(const void* p) {
    uint32_t a;
    asm("{ .reg .u64 t; cvta.to.shared.u64 t, %1; cvt.u32.u64 %0, t; }"
        : "=r"(a) : "l"(p));
    return a;
}

#define SWZ(o) ((o) ^ (((o) >> 3) & 0x70))   // SW128: 16B-granular xor swizzle

#define CPA16(sa, gp) \
    asm volatile("cp.async.cg.shared.global [%0], [%1], 16;" :: "r"(sa), "l"(gp) : "memory")
#define CPA_COMMIT() asm volatile("cp.async.commit_group;" ::: "memory")
#define CPA_WAIT(n)  asm volatile("cp.async.wait_group %0;" :: "n"(n) : "memory")

#define LDSM4(r0, r1, r2, r3, a) \
    asm volatile("ldmatrix.sync.aligned.m8n8.x4.shared.b16 {%0,%1,%2,%3}, [%4];" \
                 : "=r"(r0), "=r"(r1), "=r"(r2), "=r"(r3) : "r"(a))

// D = A*B + D, bf16 inputs, fp32 accum.  A frag 4xb32, B frag 2xb32, C 4xf32.
#define MMA(c, a0, a1, a2, a3, b0, b1) \
    asm volatile("mma.sync.aligned.m16n8k16.row.col.f32.bf16.bf16.f32 " \
                 "{%0,%1,%2,%3}, {%4,%5,%6,%7}, {%8,%9}, {%0,%1,%2,%3};" \
                 : "+f"((c)[0]), "+f"((c)[1]), "+f"((c)[2]), "+f"((c)[3]) \
                 : "r"(a0), "r"(a1), "r"(a2), "r"(a3), "r"(b0), "r"(b1))

// ---------------------------------------------------------------------------
// Pre-pass 1: gather active input cols + split fp32 -> bf16 hi/lo
// ---------------------------------------------------------------------------
__global__ void nsl_split_x(const float* __restrict__ x,
                            const int* __restrict__ in_idx) {
    const int k = blockIdx.x * blockDim.x + threadIdx.x;
    const int m = blockIdx.y;
    const int c = __ldg(&in_idx[k]);
    const float v = __ldg(&x[(size_t)m * IN_F + c]);
    const __nv_bfloat16 h = __float2bfloat16(v);
    const __nv_bfloat16 l = __float2bfloat16(v - __bfloat162float(h));
    g_Ah[(size_t)m * ACT_IN + k] = h;
    g_Al[(size_t)m * ACT_IN + k] = l;
}

// Pre-pass 2: split weight fp32 -> bf16 hi/lo
__global__ void nsl_split_w(const float* __restrict__ w) {
    const size_t i = blockIdx.x * (size_t)blockDim.x + threadIdx.x;
    const float v = __ldg(&w[i]);
    const __nv_bfloat16 h = __float2bfloat16(v);
    const __nv_bfloat16 l = __float2bfloat16(v - __bfloat162float(h));
    g_Bh[i] = h;
    g_Bl[i] = l;
}

// ---------------------------------------------------------------------------
// Main GEMM: C[m, out_idx[n]] = sum_k (Ah+Al)[m,k] * (Bh+Bl)[n,k] + bias[n]
// via 3 HMMA products with fp32 register accumulation.
// ---------------------------------------------------------------------------
__global__ __launch_bounds__(NTH, 1)
void nsl_mma(const float* __restrict__ bias,
             const int*   __restrict__ out_idx,
             float*       __restrict__ out) {
    extern __shared__ __align__(1024) char smem[];
    const uint32_t sb = smem_u32(smem);
    const int tid  = threadIdx.x;
    const int wid  = tid >> 5;
    const int lane = tid & 31;
    const int m0 = blockIdx.y * BM;
    const int n0 = blockIdx.x * BN;

    const int warp_m = wid >> 2;       // 0..1  -> 64-row slab
    const int warp_n = wid & 3;        // 0..3  -> 32-col slab

    // ---- cp.async slot mapping: per tile 128 rows x 8 x 16B = 1024 chunks,
    // 4 per thread; same (row,chunk) used for all four tiles.
    int      gOff[4];
    uint32_t sOff[4];
#pragma unroll
    for (int i = 0; i < 4; i++) {
        const int id = tid + i * NTH;
        const int r = id >> 3, cv = id & 7;
        gOff[i] = r * ACT_IN + cv * 8;                  // elements
        sOff[i] = SWZ((uint32_t)(r * 128 + cv * 16));   // swizzled bytes
    }
    const __nv_bfloat16* pAh = g_Ah + (size_t)m0 * ACT_IN;
    const __nv_bfloat16* pAl = g_Al + (size_t)m0 * ACT_IN;
    const __nv_bfloat16* pBh = g_Bh + (size_t)n0 * ACT_IN;
    const __nv_bfloat16* pBl = g_Bl + (size_t)n0 * ACT_IN;

    auto load_stage = [&](int s, int b) {
        const uint32_t base = sb + b * STAGE_BYTES;
        const int ke = s * KC;
#pragma unroll
        for (int i = 0; i < 4; i++) {
            CPA16(base + T_AH + sOff[i], pAh + ke + gOff[i]);
            CPA16(base + T_AL + sOff[i], pAl + ke + gOff[i]);
            CPA16(base + T_BH + sOff[i], pBh + ke + gOff[i]);
            CPA16(base + T_BL + sOff[i], pBl + ke + gOff[i]);
        }
        CPA_COMMIT();
    };

    // ---- ldmatrix lane addressing (within a tile, before stage/tile base) ----
    // A (x4, m16 x k16): rows m .. m+15 (lane&15), k halves by lane>>4.
    const int lrow  = lane & 15;
    const int lkoff = (lane >> 4) * 16;   // bytes

    // ---- accumulators: warp tile 64x32 = 4 m-tiles x 4 n-tiles x 4 f32 ----
    float acc[4][4][4];
#pragma unroll
    for (int i = 0; i < 4; i++)
#pragma unroll
        for (int j = 0; j < 4; j++)
#pragma unroll
            for (int q = 0; q < 4; q++) acc[i][j][q] = 0.0f;

    // ---- pipeline prologue ----
    load_stage(0, 0);
    load_stage(1, 1);

    for (int s = 0; s < NSTAGE; s++) {
        if (s < NSTAGE - 1) { CPA_WAIT(1); } else { CPA_WAIT(0); }
        __syncthreads();

        const uint32_t base = sb + (s & 1) * STAGE_BYTES;
        const uint32_t aRow = (uint32_t)((warp_m * 64 + lrow) * 128);
        const uint32_t bRow = (uint32_t)((warp_n * 32 + lrow) * 128);

#pragma unroll
        for (int ks = 0; ks < 4; ks++) {
            const uint32_t kb = (uint32_t)(ks * 32 + lkoff);

            // B-hi fragments: 2 x ldmatrix.x4 cover n32 x k16
            uint32_t bh[8];
            LDSM4(bh[0], bh[1], bh[2], bh[3], base + T_BH + SWZ(bRow + kb));
            LDSM4(bh[4], bh[5], bh[6], bh[7], base + T_BH + SWZ(bRow + 16 * 128 + kb));
            // A-hi fragments: 4 m-tiles
            uint32_t ah[4][4];
#pragma unroll
            for (int mt = 0; mt < 4; mt++)
                LDSM4(ah[mt][0], ah[mt][1], ah[mt][2], ah[mt][3],
                      base + T_AH + SWZ(aRow + (uint32_t)(mt * 16 * 128) + kb));

            // P1: Ah * Bh
#pragma unroll
            for (int mt = 0; mt < 4; mt++) {
                MMA(acc[mt][0], ah[mt][0], ah[mt][1], ah[mt][2], ah[mt][3], bh[0], bh[2]);
                MMA(acc[mt][1], ah[mt][0], ah[mt][1], ah[mt][2], ah[mt][3], bh[1], bh[3]);
                MMA(acc[mt][2], ah[mt][0], ah[mt][1], ah[mt][2], ah[mt][3], bh[4], bh[6]);
                MMA(acc[mt][3], ah[mt][0], ah[mt][1], ah[mt][2], ah[mt][3], bh[5], bh[7]);
            }

            // P2: Ah * Bl  (bl reuses regs after P2 ends)
            {
                uint32_t bl[8];
                LDSM4(bl[0], bl[1], bl[2], bl[3], base + T_BL + SWZ(bRow + kb));
                LDSM4(bl[4], bl[5], bl[6], bl[7], base + T_BL + SWZ(bRow + 16 * 128 + kb));
#pragma unroll
                for (int mt = 0; mt < 4; mt++) {
                    MMA(acc[mt][0], ah[mt][0], ah[mt][1], ah[mt][2], ah[mt][3], bl[0], bl[2]);
                    MMA(acc[mt][1], ah[mt][0], ah[mt][1], ah[mt][2], ah[mt][3], bl[1], bl[3]);
                    MMA(acc[mt][2], ah[mt][0], ah[mt][1], ah[mt][2], ah[mt][3], bl[4], bl[6]);
                    MMA(acc[mt][3], ah[mt][0], ah[mt][1], ah[mt][2], ah[mt][3], bl[5], bl[7]);
                }
            }

            // P3: Al * Bh  (al reuses ah's register space per m-tile)
#pragma unroll
            for (int mt = 0; mt < 4; mt++) {
                uint32_t al[4];
                LDSM4(al[0], al[1], al[2], al[3],
                      base + T_AL + SWZ(aRow + (uint32_t)(mt * 16 * 128) + kb));
                MMA(acc[mt][0], al[0], al[1], al[2], al[3], bh[0], bh[2]);
                MMA(acc[mt][1], al[0], al[1], al[2], al[3], bh[1], bh[3]);
                MMA(acc[mt][2], al[0], al[1], al[2], al[3], bh[4], bh[6]);
                MMA(acc[mt][3], al[0], al[1], al[2], al[3], bh[5], bh[7]);
            }
        }

        __syncthreads();                       // all warps done with buf (s&1)
        if (s + 2 < NSTAGE) load_stage(s + 2, s & 1);
    }

    // ---- epilogue: bias + scatter straight from C fragments ----
    // C frag: c0,c1 -> (row t/4, col 2*(t%4)+{0,1}); c2,c3 -> row+8.
    const int trow = lane >> 2;
    const int tcol = (lane & 3) * 2;
    int   oc0[4], oc1[4];
    float bv0[4], bv1[4];
#pragma unroll
    for (int nt = 0; nt < 4; nt++) {
        const int n = n0 + warp_n * 32 + nt * 8 + tcol;
        oc0[nt] = __ldg(&out_idx[n]);     oc1[nt] = __ldg(&out_idx[n + 1]);
        bv0[nt] = __ldg(&bias[n]);        bv1[nt] = __ldg(&bias[n + 1]);
    }
#pragma unroll
    for (int mt = 0; mt < 4; mt++) {
        const int m = m0 + warp_m * 64 + mt * 16 + trow;
        float* r0 = out + (size_t)m * OUT_F;
        float* r1 = out + (size_t)(m + 8) * OUT_F;
#pragma unroll
        for (int nt = 0; nt < 4; nt++) {
            r0[oc0[nt]] = acc[mt][nt][0] + bv0[nt];
            r0[oc1[nt]] = acc[mt][nt][1] + bv1[nt];
            r1[oc0[nt]] = acc[mt][nt][2] + bv0[nt];
            r1[oc1[nt]] = acc[mt][nt][3] + bv1[nt];
        }
    }
}

// ---------------------------------------------------------------------------
// Launch
// ---------------------------------------------------------------------------
extern "C" void kernel_launch(void* const* d_in, const int* in_sizes, int n_in,
                              void* d_out, int out_size) {
    const float* x       = (const float*)d_in[0];
    const float* weight  = (const float*)d_in[1];
    const float* bias    = (const float*)d_in[2];
    const int*   in_idx  = (const int*)d_in[3];
    const int*   out_idx = (const int*)d_in[4];
    float* out = (float*)d_out;

    // zero full output (inactive columns must be 0; buffer is poisoned)
    cudaMemsetAsync(out, 0, (size_t)out_size * sizeof(float), 0);

    // pre-pass: gather + bf16 split
    {
        dim3 g(ACT_IN / 256, NROWS);
        nsl_split_x<<<g, 256>>>(x, in_idx);
    }
    nsl_split_w<<<(ACT_OUT * ACT_IN) / 256, 256>>>(weight);

    // tensor-core GEMM (mma.sync) + bias + scatter
    cudaFuncSetAttribute(nsl_mma, cudaFuncAttributeMaxDynamicSharedMemorySize,
                         SMEM_TOTAL);
    dim3 grid(ACT_OUT / BN, NROWS / BM);   // 64 x 64
    nsl_mma<<<grid, NTH, SMEM_TOTAL>>>(bias, out_idx, out);
}